// round 11
// baseline (speedup 1.0000x reference)
#include <cuda_runtime.h>
#include <cuda_bf16.h>
#include <math.h>
#include <stdint.h>

#define B_   4
#define S_   2048
#define E_   1024
#define H_   16
#define DH_  64
#define BH_  (B_*H_)
#define M_   (B_*S_)
#define PA   40      // smem pitch (bf16) KC=32 tiles (80B rows)
#define PS   72      // smem pitch (bf16) KC=64 tiles (144B rows)
#define PV   72      // smem pitch (bf16) 32x64 V tiles

// ---- smem geometry ----
#define TQA (256*PA*2)            // 20480 A tile (256x32)
#define TQB (128*PA*2)            // 10240 B tile (128x32)
#define QBUF (2*TQA+2*TQB)        // 61440 per buffer {Ah,Al,Bh,Bl}
#define DSM_Q 135168              // max(2*QBUF, 256*132*4 epilogue)
#define TSA (256*PS*2)            // 36864
#define TSB (128*PS*2)            // 18432
#define DSM_S (2*TSA+2*TSB)       // 110592
#define TPP (256*PA*2)            // 20480 P tile
#define TPV (32*PV*2)             // 4608  V tile
#define PVBUF (2*TPP+2*TPV)       // 50176
#define DSM_P (2*PVBUF)           // 100352
#define EPIT 132                  // fp32 epilogue pitch

// ---- device scratch (allocation-free) ----
__device__ __nv_bfloat16 g_Xh[(size_t)3*M_*E_], g_Xl[(size_t)3*M_*E_];   // pre-split q,k,v
__device__ __nv_bfloat16 g_Wh[(size_t)4*E_*E_], g_Wl[(size_t)4*E_*E_];   // wq,wk,wv,wo
__device__ __nv_bfloat16 g_Qh[BH_*S_*DH_], g_Ql[BH_*S_*DH_];
__device__ __nv_bfloat16 g_Kh[BH_*S_*DH_], g_Kl[BH_*S_*DH_];
__device__ __nv_bfloat16 g_Vh[BH_*S_*DH_], g_Vl[BH_*S_*DH_];
__device__ __nv_bfloat16 g_Ch[(size_t)M_*E_], g_Cl[(size_t)M_*E_];
__device__ float g_m[BH_*S_], g_linv[BH_*S_];   // softmax row stats

static __device__ __forceinline__ uint32_t s2u(const void* p) {
    return (uint32_t)__cvta_generic_to_shared(p);
}
static __device__ __forceinline__ void cpa16(uint32_t d, const void* s) {
    asm volatile("cp.async.cg.shared.global [%0], [%1], 16;" :: "r"(d), "l"(s));
}
static __device__ __forceinline__ void cpa_commit() {
    asm volatile("cp.async.commit_group;");
}
template<int N> static __device__ __forceinline__ void cpa_wait() {
    asm volatile("cp.async.wait_group %0;" :: "n"(N));
}
static __device__ __forceinline__ void ldsm4(uint32_t* r, uint32_t a) {
    asm volatile("ldmatrix.sync.aligned.m8n8.x4.shared.b16 {%0,%1,%2,%3}, [%4];\n"
        : "=r"(r[0]), "=r"(r[1]), "=r"(r[2]), "=r"(r[3]) : "r"(a));
}
static __device__ __forceinline__ void ldsm4t(uint32_t* r, uint32_t a) {
    asm volatile("ldmatrix.sync.aligned.m8n8.x4.trans.shared.b16 {%0,%1,%2,%3}, [%4];\n"
        : "=r"(r[0]), "=r"(r[1]), "=r"(r[2]), "=r"(r[3]) : "r"(a));
}
static __device__ __forceinline__ void mma16816(float* c, const uint32_t* a, const uint32_t* b) {
    asm("mma.sync.aligned.m16n8k16.row.col.f32.bf16.bf16.f32 "
        "{%0,%1,%2,%3}, {%4,%5,%6,%7}, {%8,%9}, {%0,%1,%2,%3};\n"
        : "+f"(c[0]), "+f"(c[1]), "+f"(c[2]), "+f"(c[3])
        : "r"(a[0]), "r"(a[1]), "r"(a[2]), "r"(a[3]), "r"(b[0]), "r"(b[1]));
}
static __device__ __forceinline__ void split2(float a, float b, uint32_t& hi, uint32_t& lo) {
    __nv_bfloat16 ha = __float2bfloat16(a), hb = __float2bfloat16(b);
    __nv_bfloat16 la = __float2bfloat16(a - __bfloat162float(ha));
    __nv_bfloat16 lb = __float2bfloat16(b - __bfloat162float(hb));
    __nv_bfloat162 Hh; Hh.x = ha; Hh.y = hb; hi = *(uint32_t*)&Hh;
    __nv_bfloat162 Ll; Ll.x = la; Ll.y = lb; lo = *(uint32_t*)&Ll;
}
static __device__ __forceinline__ void split8(const float4& x0, const float4& x1,
                                              uint4& H, uint4& L) {
    split2(x0.x, x0.y, H.x, L.x);
    split2(x0.z, x0.w, H.y, L.y);
    split2(x1.x, x1.y, H.z, L.z);
    split2(x1.z, x1.w, H.w, L.w);
}

// 64x64 warp tile over a staged chunk. acc[4 mf][8 nf][4].
template<int PITCH, int KSTEPS>
static __device__ __forceinline__ void compute64(
    const __nv_bfloat16* Ah, const __nv_bfloat16* Al,
    const __nv_bfloat16* Bh, const __nv_bfloat16* Bl,
    float (&acc)[4][8][4], int wm, int wn, int lane)
{
    const int arow = wm * 64 + (lane & 15);
    const int brow = wn * 64 + (lane & 7) + ((lane & 16) ? 8 : 0);
#pragma unroll
    for (int s = 0; s < KSTEPS; s++) {
        const int ak = s * 16 + ((lane & 16) ? 8 : 0);
        const int bk = s * 16 + ((lane & 8) ? 8 : 0);
        uint32_t ah[4][4], al[4][4];
#pragma unroll
        for (int mf = 0; mf < 4; mf++) {
            ldsm4(ah[mf], s2u(&Ah[(arow + 16 * mf) * PITCH + ak]));
            ldsm4(al[mf], s2u(&Al[(arow + 16 * mf) * PITCH + ak]));
        }
#pragma unroll
        for (int j = 0; j < 4; j++) {
            uint32_t th[4], tl[4];
            ldsm4(th, s2u(&Bh[(brow + 16 * j) * PITCH + bk]));
            ldsm4(tl, s2u(&Bl[(brow + 16 * j) * PITCH + bk]));
#pragma unroll
            for (int mf = 0; mf < 4; mf++) {
                mma16816(acc[mf][2*j],   ah[mf], th);
                mma16816(acc[mf][2*j+1], ah[mf], th + 2);
                mma16816(acc[mf][2*j],   al[mf], th);
                mma16816(acc[mf][2*j+1], al[mf], th + 2);
                mma16816(acc[mf][2*j],   ah[mf], tl);
                mma16816(acc[mf][2*j+1], ah[mf], tl + 2);
            }
        }
    }
}

// ---------------------------------------------------------------------------
// Kernel 0: pre-split q,k,v and the 4 weights into bf16 hi/lo. grid(4096,7).
// ---------------------------------------------------------------------------
__global__ __launch_bounds__(256) void k_presplit(
    const float* __restrict__ q, const float* __restrict__ k, const float* __restrict__ v,
    const float* __restrict__ wq, const float* __restrict__ wk,
    const float* __restrict__ wv, const float* __restrict__ wo)
{
    const int z = blockIdx.y;
    const float* src;
    __nv_bfloat16 *dh, *dl;
    size_t n;
    if (z < 3) {
        src = (z == 0) ? q : (z == 1) ? k : v;
        dh = g_Xh + (size_t)z * M_ * E_;
        dl = g_Xl + (size_t)z * M_ * E_;
        n = (size_t)M_ * E_;
    } else {
        int w = z - 3;
        src = (w == 0) ? wq : (w == 1) ? wk : (w == 2) ? wv : wo;
        dh = g_Wh + (size_t)w * E_ * E_;
        dl = g_Wl + (size_t)w * E_ * E_;
        n = (size_t)E_ * E_;
    }
    size_t base = ((size_t)blockIdx.x * 256 + threadIdx.x) * 8;
    if (base >= n) return;
    float4 x0 = *(const float4*)&src[base];
    float4 x1 = *(const float4*)&src[base + 4];
    uint4 H, L;
    split8(x0, x1, H, L);
    *(uint4*)&dh[base] = H;
    *(uint4*)&dl[base] = L;
}

// ---------------------------------------------------------------------------
// Kernel 1: QKV projections. block 256x128, 256 thr, cp.async pipelined.
// ---------------------------------------------------------------------------
__global__ __launch_bounds__(256) void k_qkv(
    const float* __restrict__ bq, const float* __restrict__ bk, const float* __restrict__ bv)
{
    extern __shared__ char dsm[];
    const int z = blockIdx.z;
    const __nv_bfloat16* Xh = g_Xh + (size_t)z * M_ * E_;
    const __nv_bfloat16* Xl = g_Xl + (size_t)z * M_ * E_;
    const __nv_bfloat16* Wh = g_Wh + (size_t)z * E_ * E_;
    const __nv_bfloat16* Wl = g_Wl + (size_t)z * E_ * E_;
    const float* bias = (z == 0) ? bq : (z == 1) ? bk : bv;
    __nv_bfloat16* dsth = (z == 0) ? g_Qh : (z == 1) ? g_Kh : g_Vh;
    __nv_bfloat16* dstl = (z == 0) ? g_Ql : (z == 1) ? g_Kl : g_Vl;

    const int tid = threadIdx.x, wid = tid >> 5, lane = tid & 31;
    const int wm = wid >> 1, wn = wid & 1;
    const int row0 = blockIdx.x * 256, col0 = blockIdx.y * 128;

    auto stage = [&](int buf, int kt) {
        uint32_t sb = s2u(dsm) + buf * QBUF;
#pragma unroll
        for (int i = 0; i < 4; i++) {
            int ch = tid + i * 256;
            int r = ch >> 2, c = ch & 3;
            uint32_t d = sb + r * (PA * 2) + c * 16;
            size_t so = (size_t)(row0 + r) * E_ + kt + c * 8;
            cpa16(d, Xh + so);
            cpa16(d + TQA, Xl + so);
        }
#pragma unroll
        for (int i = 0; i < 2; i++) {
            int ch = tid + i * 256;
            int r = ch >> 2, c = ch & 3;
            uint32_t d = sb + 2 * TQA + r * (PA * 2) + c * 16;
            size_t so = (size_t)(col0 + r) * E_ + kt + c * 8;
            cpa16(d, Wh + so);
            cpa16(d + TQB, Wl + so);
        }
    };

    float acc[4][8][4];
#pragma unroll
    for (int a = 0; a < 4; a++)
#pragma unroll
        for (int bn = 0; bn < 8; bn++)
#pragma unroll
            for (int e = 0; e < 4; e++) acc[a][bn][e] = 0.f;

    stage(0, 0); cpa_commit();
    cpa_wait<0>(); __syncthreads();

    const int NCH = E_ / 32;
    for (int c = 0; c < NCH; c++) {
        if (c + 1 < NCH) { stage((c + 1) & 1, (c + 1) * 32); cpa_commit(); }
        char* bb = dsm + (c & 1) * QBUF;
        compute64<PA, 2>((__nv_bfloat16*)bb, (__nv_bfloat16*)(bb + TQA),
                         (__nv_bfloat16*)(bb + 2 * TQA), (__nv_bfloat16*)(bb + 2 * TQA + TQB),
                         acc, wm, wn, lane);
        if (c + 1 < NCH) { cpa_wait<0>(); __syncthreads(); }
    }
    __syncthreads();

    // epilogue via smem fp32
    float* st = (float*)dsm;
    const int g = lane >> 2, c2 = (lane & 3) * 2;
#pragma unroll
    for (int mf = 0; mf < 4; mf++)
#pragma unroll
        for (int nf = 0; nf < 8; nf++) {
            int row = wm * 64 + mf * 16 + g, col = wn * 64 + nf * 8 + c2;
            *(float2*)&st[row * EPIT + col] = make_float2(acc[mf][nf][0], acc[mf][nf][1]);
            *(float2*)&st[(row + 8) * EPIT + col] = make_float2(acc[mf][nf][2], acc[mf][nf][3]);
        }
    __syncthreads();
#pragma unroll
    for (int i = 0; i < 16; i++) {
        int idx = tid + i * 256;          // 4096 groups of 8 cols
        int g8 = idx & 15, m = idx >> 4;
        int cbase = g8 * 8;
        float4 x0 = *(float4*)&st[m * EPIT + cbase];
        float4 x1 = *(float4*)&st[m * EPIT + cbase + 4];
        int n0 = col0 + cbase;
        x0.x += __ldg(&bias[n0]);     x0.y += __ldg(&bias[n0 + 1]);
        x0.z += __ldg(&bias[n0 + 2]); x0.w += __ldg(&bias[n0 + 3]);
        x1.x += __ldg(&bias[n0 + 4]); x1.y += __ldg(&bias[n0 + 5]);
        x1.z += __ldg(&bias[n0 + 6]); x1.w += __ldg(&bias[n0 + 7]);
        uint4 Hv, Lv;
        split8(x0, x1, Hv, Lv);
        int mm = row0 + m;
        int b = mm >> 11, s = mm & (S_ - 1);
        int hd = n0 >> 6, d = n0 & 63;
        size_t o = (((size_t)(b * H_ + hd)) * S_ + s) * DH_ + d;
        *(uint4*)&dsth[o] = Hv;
        *(uint4*)&dstl[o] = Lv;
    }
}

// ---------------------------------------------------------------------------
// Kernel 2: scores = Q K^T / 8, causal. block 256x128. grid(8,16,64).
// ---------------------------------------------------------------------------
__global__ __launch_bounds__(256) void k_scores(float* __restrict__ attn)
{
    extern __shared__ char dsm[];
    const int qt = blockIdx.x, kt = blockIdx.y, bhd = blockIdx.z;
    const int row0 = qt * 256, col0 = kt * 128;
    float* A = attn + (size_t)bhd * S_ * S_;
    const int tid = threadIdx.x;

    if (col0 >= row0 + 256) {            // fully masked: final attn value is 0
        float4 z = make_float4(0.f, 0.f, 0.f, 0.f);
#pragma unroll
        for (int i = 0; i < 32; i++) {
            int idx = tid + i * 256;
            int r = idx >> 5, c4 = (idx & 31) * 4;
            *(float4*)&A[(size_t)(row0 + r) * S_ + col0 + c4] = z;
        }
        return;
    }

    const __nv_bfloat16* Qh = g_Qh + (size_t)bhd * S_ * DH_;
    const __nv_bfloat16* Ql = g_Ql + (size_t)bhd * S_ * DH_;
    const __nv_bfloat16* Kh = g_Kh + (size_t)bhd * S_ * DH_;
    const __nv_bfloat16* Kl = g_Kl + (size_t)bhd * S_ * DH_;
    const int wid = tid >> 5, lane = tid & 31;
    const int wm = wid >> 1, wn = wid & 1;

    {   // single-shot staging of Q(256x64) and K(128x64) hi/lo
        uint32_t sb = s2u(dsm);
#pragma unroll
        for (int i = 0; i < 8; i++) {
            int ch = tid + i * 256;
            int r = ch >> 3, c = ch & 7;
            uint32_t d = sb + r * (PS * 2) + c * 16;
            size_t so = (size_t)(row0 + r) * DH_ + c * 8;
            cpa16(d, Qh + so);
            cpa16(d + TSA, Ql + so);
        }
#pragma unroll
        for (int i = 0; i < 4; i++) {
            int ch = tid + i * 256;
            int r = ch >> 3, c = ch & 7;
            uint32_t d = sb + 2 * TSA + r * (PS * 2) + c * 16;
            size_t so = (size_t)(col0 + r) * DH_ + c * 8;
            cpa16(d, Kh + so);
            cpa16(d + TSB, Kl + so);
        }
        cpa_commit();
    }
    cpa_wait<0>(); __syncthreads();

    float acc[4][8][4];
#pragma unroll
    for (int a = 0; a < 4; a++)
#pragma unroll
        for (int bn = 0; bn < 8; bn++)
#pragma unroll
            for (int e = 0; e < 4; e++) acc[a][bn][e] = 0.f;

    compute64<PS, 4>((__nv_bfloat16*)dsm, (__nv_bfloat16*)(dsm + TSA),
                     (__nv_bfloat16*)(dsm + 2 * TSA), (__nv_bfloat16*)(dsm + 2 * TSA + TSB),
                     acc, wm, wn, lane);

    const int g = lane >> 2, c2 = (lane & 3) * 2;
#pragma unroll
    for (int mf = 0; mf < 4; mf++)
#pragma unroll
        for (int nf = 0; nf < 8; nf++)
#pragma unroll
            for (int eh = 0; eh < 2; eh++) {
                int gi = row0 + wm * 64 + mf * 16 + g + eh * 8;
                int gj = col0 + wn * 64 + nf * 8 + c2;
                // masked: -1e30 within gi's own 128-col group (exp -> 0 in stats),
                // 0 beyond (never read by stats; pv masks by col<=row itself).
                float m0 = ((gj >> 7) == (gi >> 7)) ? -1e30f : 0.0f;
                float m1 = (((gj + 1) >> 7) == (gi >> 7)) ? -1e30f : 0.0f;
                float v0 = (gj <= gi) ? acc[mf][nf][eh * 2] * 0.125f : m0;
                float v1 = (gj + 1 <= gi) ? acc[mf][nf][eh * 2 + 1] * 0.125f : m1;
                *(float2*)&A[(size_t)gi * S_ + gj] = make_float2(v0, v1);
            }
}

// ---------------------------------------------------------------------------
// Kernel 3: row softmax STATS only (m, 1/l). No write-back of the big buffer.
// One block per row, reads the causal prefix of raw scores.
// ---------------------------------------------------------------------------
__global__ __launch_bounds__(256) void k_stats(const float* __restrict__ attn)
{
    const int s = blockIdx.x & (S_ - 1);
    const int ncols4 = ((s >> 7) + 1) * 32;
    const float4* p = (const float4*)(attn + (size_t)blockIdx.x * S_);
    const int t = threadIdx.x;
    __shared__ float red[256];

    float4 a0 = make_float4(-1e30f, -1e30f, -1e30f, -1e30f);
    float4 a1 = a0;
    const bool v0 = t < ncols4, v1 = (t + 256) < ncols4;
    if (v0) a0 = p[t];
    if (v1) a1 = p[t + 256];

    float m = fmaxf(fmaxf(fmaxf(a0.x, a0.y), fmaxf(a0.z, a0.w)),
                    fmaxf(fmaxf(a1.x, a1.y), fmaxf(a1.z, a1.w)));
    red[t] = m; __syncthreads();
    for (int st = 128; st > 0; st >>= 1) {
        if (t < st) red[t] = fmaxf(red[t], red[t + st]);
        __syncthreads();
    }
    m = red[0]; __syncthreads();

    float sum = 0.f;
    if (v0) sum += __expf(a0.x - m) + __expf(a0.y - m) + __expf(a0.z - m) + __expf(a0.w - m);
    if (v1) sum += __expf(a1.x - m) + __expf(a1.y - m) + __expf(a1.z - m) + __expf(a1.w - m);
    red[t] = sum; __syncthreads();
    for (int st = 128; st > 0; st >>= 1) {
        if (t < st) red[t] += red[t + st];
        __syncthreads();
    }
    if (t == 0) {
        g_m[blockIdx.x] = m;
        g_linv[blockIdx.x] = 1.f / red[0];
    }
}

// ---------------------------------------------------------------------------
// Kernel 4: fused normalize + context = softmax(S) @ V. Reads raw scores,
// writes final probs back to attn in place, accumulates PV. grid(8,1,64).
// ---------------------------------------------------------------------------
__global__ __launch_bounds__(256) void k_pv(float* __restrict__ attn)
{
    extern __shared__ char dsm[];
    const int qt = blockIdx.x, bhd = blockIdx.z;
    const int row0 = qt * 256;
    float* P = attn + (size_t)bhd * S_ * S_;
    const __nv_bfloat16* Vh = g_Vh + (size_t)bhd * S_ * DH_;
    const __nv_bfloat16* Vl = g_Vl + (size_t)bhd * S_ * DH_;
    const int b = bhd >> 4, hd = bhd & 15;

    const int tid = threadIdx.x, wid = tid >> 5, lane = tid & 31;
    const int wm = wid >> 1, wn = wid & 1;

    // P register staging: 8 rows per thread, fixed across chunks
    const int pr = tid >> 3, pc4 = (tid & 7) * 4;
    float mrow[8], lrow[8];
#pragma unroll
    for (int i = 0; i < 8; i++) {
        int row = row0 + pr + i * 32;
        mrow[i] = g_m[(size_t)bhd * S_ + row];
        lrow[i] = g_linv[(size_t)bhd * S_ + row];
    }

    float4 rp[8];
    auto loadP = [&](int kt) {
#pragma unroll
        for (int i = 0; i < 8; i++)
            rp[i] = *(const float4*)&P[(size_t)(row0 + pr + i * 32) * S_ + kt + pc4];
    };
    // Convert raw scores -> final probs; write probs to attn AND split into smem.
    auto storeP = [&](int buf, int kt) {
        char* pb = dsm + buf * PVBUF;
        const int colb = kt + pc4;
#pragma unroll
        for (int i = 0; i < 8; i++) {
            const int row = row0 + pr + i * 32;
            const float m = mrow[i], li = lrow[i];
            float4 pv;
            pv.x = (colb + 0 <= row) ? __expf(rp[i].x - m) * li : 0.f;
            pv.y = (colb + 1 <= row) ? __expf(rp[i].y - m) * li : 0.f;
            pv.z = (colb + 2 <= row) ? __expf(rp[i].z - m) * li : 0.f;
            pv.w = (colb + 3 <= row) ? __expf(rp[i].w - m) * li : 0.f;
            *(float4*)&P[(size_t)row * S_ + colb] = pv;   // final attn probs
            uint32_t h0, l0, h1, l1;
            split2(pv.x, pv.y, h0, l0);
            split2(pv.z, pv.w, h1, l1);
            int off = ((pr + i * 32) * PA + pc4) * 2;
            *(uint2*)(pb + off) = make_uint2(h0, h1);
            *(uint2*)(pb + TPP + off) = make_uint2(l0, l1);
        }
    };
    auto stageV = [&](int buf, int kt) {
        uint32_t vb = s2u(dsm) + buf * PVBUF + 2 * TPP;
        int r = tid >> 3, c = tid & 7;
        uint32_t d = vb + r * (PV * 2) + c * 16;
        size_t so = (size_t)(kt + r) * DH_ + c * 8;
        cpa16(d, Vh + so);
        cpa16(d + TPV, Vl + so);
    };

    float acc[4][4][4];
#pragma unroll
    for (int a = 0; a < 4; a++)
#pragma unroll
        for (int bn = 0; bn < 4; bn++)
#pragma unroll
            for (int e = 0; e < 4; e++) acc[a][bn][e] = 0.f;

    loadP(0); storeP(0, 0); stageV(0, 0); cpa_commit();
    cpa_wait<0>(); __syncthreads();

    const int NCH = (row0 + 256) / 32;       // causal bound
    const int arow = wm * 64 + (lane & 15);
    const int vcol = wn * 32 + ((lane & 16) ? 8 : 0);
    for (int c = 0; c < NCH; c++) {
        if (c + 1 < NCH) { loadP((c + 1) * 32); stageV((c + 1) & 1, (c + 1) * 32); cpa_commit(); }
        char* pb = dsm + (c & 1) * PVBUF;
        const __nv_bfloat16* Ph = (__nv_bfloat16*)pb;
        const __nv_bfloat16* Pl = (__nv_bfloat16*)(pb + TPP);
        const __nv_bfloat16* Vsh = (__nv_bfloat16*)(pb + 2 * TPP);
        const __nv_bfloat16* Vsl = (__nv_bfloat16*)(pb + 2 * TPP + TPV);
#pragma unroll
        for (int ks = 0; ks < 32; ks += 16) {
            const int ak = ks + ((lane & 16) ? 8 : 0);
            const int vrow = ks + (lane & 7) + ((lane & 8) ? 8 : 0);
            uint32_t ah[4][4], al[4][4];
#pragma unroll
            for (int mf = 0; mf < 4; mf++) {
                ldsm4(ah[mf], s2u(&Ph[(arow + 16 * mf) * PA + ak]));
                ldsm4(al[mf], s2u(&Pl[(arow + 16 * mf) * PA + ak]));
            }
#pragma unroll
            for (int j = 0; j < 2; j++) {
                uint32_t th[4], tl[4];
                ldsm4t(th, s2u(&Vsh[vrow * PV + vcol + 16 * j]));
                ldsm4t(tl, s2u(&Vsl[vrow * PV + vcol + 16 * j]));
#pragma unroll
                for (int mf = 0; mf < 4; mf++) {
                    mma16816(acc[mf][2*j],   ah[mf], th);
                    mma16816(acc[mf][2*j+1], ah[mf], th + 2);
                    mma16816(acc[mf][2*j],   al[mf], th);
                    mma16816(acc[mf][2*j+1], al[mf], th + 2);
                    mma16816(acc[mf][2*j],   ah[mf], tl);
                    mma16816(acc[mf][2*j+1], ah[mf], tl + 2);
                }
            }
        }
        if (c + 1 < NCH) { storeP((c + 1) & 1, (c + 1) * 32); cpa_wait<0>(); __syncthreads(); }
    }

    const int g = lane >> 2, c2 = (lane & 3) * 2;
#pragma unroll
    for (int mf = 0; mf < 4; mf++)
#pragma unroll
        for (int nf = 0; nf < 4; nf++) {
            int row = row0 + wm * 64 + mf * 16 + g;
            int col = wn * 32 + nf * 8 + c2;
            size_t o = ((size_t)(b * S_ + row)) * E_ + hd * DH_ + col;
            uint32_t h, l;
            split2(acc[mf][nf][0], acc[mf][nf][1], h, l);
            *(uint32_t*)&g_Ch[o] = h; *(uint32_t*)&g_Cl[o] = l;
            split2(acc[mf][nf][2], acc[mf][nf][3], h, l);
            *(uint32_t*)&g_Ch[o + 8 * E_] = h; *(uint32_t*)&g_Cl[o + 8 * E_] = l;
        }
}

// ---------------------------------------------------------------------------
// Kernel 5: out = Ctx @ wo^T + bo. Same skeleton as k_qkv. grid(32,8).
// ---------------------------------------------------------------------------
__global__ __launch_bounds__(256) void k_oproj(
    const float* __restrict__ bo, float* __restrict__ out)
{
    extern __shared__ char dsm[];
    const __nv_bfloat16* Wh = g_Wh + (size_t)3 * E_ * E_;
    const __nv_bfloat16* Wl = g_Wl + (size_t)3 * E_ * E_;

    const int tid = threadIdx.x, wid = tid >> 5, lane = tid & 31;
    const int wm = wid >> 1, wn = wid & 1;
    const int row0 = blockIdx.x * 256, col0 = blockIdx.y * 128;

    auto stage = [&](int buf, int kt) {
        uint32_t sb = s2u(dsm) + buf * QBUF;
#pragma unroll
        for (int i = 0; i < 4; i++) {
            int ch = tid + i * 256;
            int r = ch >> 2, c = ch & 3;
            uint32_t d = sb + r * (PA * 2) + c * 16;
            size_t so = (size_t)(row0 + r) * E_ + kt + c * 8;
            cpa16(d, g_Ch + so);
            cpa16(d + TQA, g_Cl + so);
        }
#pragma unroll
        for (int i = 0; i < 2; i++) {
            int ch = tid + i * 256;
            int r = ch >> 2, c = ch & 3;
            uint32_t d = sb + 2 * TQA + r * (PA * 2) + c * 16;
            size_t so = (size_t)(col0 + r) * E_ + kt + c * 8;
            cpa16(d, Wh + so);
            cpa16(d + TQB, Wl + so);
        }
    };

    float acc[4][8][4];
#pragma unroll
    for (int a = 0; a < 4; a++)
#pragma unroll
        for (int bn = 0; bn < 8; bn++)
#pragma unroll
            for (int e = 0; e < 4; e++) acc[a][bn][e] = 0.f;

    stage(0, 0); cpa_commit();
    cpa_wait<0>(); __syncthreads();

    const int NCH = E_ / 32;
    for (int c = 0; c < NCH; c++) {
        if (c + 1 < NCH) { stage((c + 1) & 1, (c + 1) * 32); cpa_commit(); }
        char* bb = dsm + (c & 1) * QBUF;
        compute64<PA, 2>((__nv_bfloat16*)bb, (__nv_bfloat16*)(bb + TQA),
                         (__nv_bfloat16*)(bb + 2 * TQA), (__nv_bfloat16*)(bb + 2 * TQA + TQB),
                         acc, wm, wn, lane);
        if (c + 1 < NCH) { cpa_wait<0>(); __syncthreads(); }
    }
    __syncthreads();

    float* st = (float*)dsm;
    const int g = lane >> 2, c2 = (lane & 3) * 2;
#pragma unroll
    for (int mf = 0; mf < 4; mf++)
#pragma unroll
        for (int nf = 0; nf < 8; nf++) {
            int row = wm * 64 + mf * 16 + g, col = wn * 64 + nf * 8 + c2;
            *(float2*)&st[row * EPIT + col] = make_float2(acc[mf][nf][0], acc[mf][nf][1]);
            *(float2*)&st[(row + 8) * EPIT + col] = make_float2(acc[mf][nf][2], acc[mf][nf][3]);
        }
    __syncthreads();
#pragma unroll
    for (int i = 0; i < 32; i++) {
        int idx = tid + i * 256;                 // 8192 float4 groups
        int c4 = idx & 31, m = idx >> 5;
        float4 x = *(float4*)&st[m * EPIT + c4 * 4];
        int n0 = col0 + c4 * 4;
        x.x += __ldg(&bo[n0]);     x.y += __ldg(&bo[n0 + 1]);
        x.z += __ldg(&bo[n0 + 2]); x.w += __ldg(&bo[n0 + 3]);
        *(float4*)&out[(size_t)(row0 + m) * E_ + n0] = x;
    }
}

// ---------------------------------------------------------------------------
extern "C" void kernel_launch(void* const* d_in, const int* in_sizes, int n_in,
                              void* d_out, int out_size)
{
    const float* q  = (const float*)d_in[0];
    const float* k  = (const float*)d_in[1];
    const float* v  = (const float*)d_in[2];
    const float* wq = (const float*)d_in[3];
    const float* bq = (const float*)d_in[4];
    const float* wk = (const float*)d_in[5];
    const float* bk = (const float*)d_in[6];
    const float* wv = (const float*)d_in[7];
    const float* bv = (const float*)d_in[8];
    const float* wo = (const float*)d_in[9];
    const float* bo = (const float*)d_in[10];

    float* out  = (float*)d_out;                       // [B,S,E]
    float* attn = out + (size_t)B_ * S_ * E_;          // [B,H,S,S]

    cudaFuncSetAttribute(k_qkv,    cudaFuncAttributeMaxDynamicSharedMemorySize, DSM_Q);
    cudaFuncSetAttribute(k_scores, cudaFuncAttributeMaxDynamicSharedMemorySize, DSM_S);
    cudaFuncSetAttribute(k_pv,     cudaFuncAttributeMaxDynamicSharedMemorySize, DSM_P);
    cudaFuncSetAttribute(k_oproj,  cudaFuncAttributeMaxDynamicSharedMemorySize, DSM_Q);

    k_presplit<<<dim3(4096, 7), 256>>>(q, k, v, wq, wk, wv, wo);
    k_qkv    <<<dim3(M_/256, E_/128, 3), 256, DSM_Q>>>(bq, bk, bv);
    k_scores <<<dim3(S_/256, S_/128, BH_), 256, DSM_S>>>(attn);
    k_stats  <<<dim3(BH_*S_), 256>>>(attn);
    k_pv     <<<dim3(S_/256, 1, BH_), 256, DSM_P>>>(attn);
    k_oproj  <<<dim3(M_/256, E_/128), 256, DSM_Q>>>(bo, out);
}

// round 12
// speedup vs baseline: 1.1850x; 1.1850x over previous
#include <cuda_runtime.h>
#include <cuda_bf16.h>
#include <math.h>
#include <stdint.h>

#define B_   4
#define S_   2048
#define E_   1024
#define H_   16
#define DH_  64
#define BH_  (B_*H_)
#define M_   (B_*S_)
#define PA   40      // smem pitch (bf16) KC=32 tiles for dense GEMMs
#define EPIT 132     // fp32 epilogue pitch

// ---- dense-GEMM smem geometry (qkv / oproj) ----
#define TQA (256*PA*2)            // 20480 A tile (256x32)
#define TQB (128*PA*2)            // 10240 B tile (128x32)
#define QBUF (2*TQA+2*TQB)        // 61440 per buffer {Ah,Al,Bh,Bl}
#define DSM_Q 135168              // max(2*QBUF, 256*132*4 epilogue)

// ---- attention smem geometry (128x64 bf16 tiles, 144B pitch) ----
#define PSB   144                 // bytes per staged row
#define THL   (128*PSB)           // 18432: one hi or lo half-tile
#define TPAIR (2*THL)             // 36864: hi+lo tile
#define DSM_ST (3*TPAIR)          // 110592: Q + 2 K bufs   (2 CTAs/SM)
#define DSM_AT (5*TPAIR)          // 184320: Q + 2 K + 2 V  (1 CTA/SM)

// ---- device scratch (allocation-free) ----
__device__ __nv_bfloat16 g_Xh[(size_t)3*M_*E_], g_Xl[(size_t)3*M_*E_];   // pre-split q,k,v
__device__ __nv_bfloat16 g_Wh[(size_t)4*E_*E_], g_Wl[(size_t)4*E_*E_];   // wq,wk,wv,wo
__device__ __nv_bfloat16 g_Qh[BH_*S_*DH_], g_Ql[BH_*S_*DH_];
__device__ __nv_bfloat16 g_Kh[BH_*S_*DH_], g_Kl[BH_*S_*DH_];
__device__ __nv_bfloat16 g_Vh[BH_*S_*DH_], g_Vl[BH_*S_*DH_];
__device__ __nv_bfloat16 g_Ch[(size_t)M_*E_], g_Cl[(size_t)M_*E_];
__device__ float g_m[(size_t)BH_*S_], g_linv[(size_t)BH_*S_];

static __device__ __forceinline__ uint32_t s2u(const void* p) {
    return (uint32_t)__cvta_generic_to_shared(p);
}
static __device__ __forceinline__ void cpa16(uint32_t d, const void* s) {
    asm volatile("cp.async.cg.shared.global [%0], [%1], 16;" :: "r"(d), "l"(s));
}
static __device__ __forceinline__ void cpa_commit() {
    asm volatile("cp.async.commit_group;");
}
template<int N> static __device__ __forceinline__ void cpa_wait() {
    asm volatile("cp.async.wait_group %0;" :: "n"(N));
}
static __device__ __forceinline__ void ldsm4(uint32_t* r, uint32_t a) {
    asm volatile("ldmatrix.sync.aligned.m8n8.x4.shared.b16 {%0,%1,%2,%3}, [%4];\n"
        : "=r"(r[0]), "=r"(r[1]), "=r"(r[2]), "=r"(r[3]) : "r"(a));
}
static __device__ __forceinline__ void ldsm4t(uint32_t* r, uint32_t a) {
    asm volatile("ldmatrix.sync.aligned.m8n8.x4.trans.shared.b16 {%0,%1,%2,%3}, [%4];\n"
        : "=r"(r[0]), "=r"(r[1]), "=r"(r[2]), "=r"(r[3]) : "r"(a));
}
static __device__ __forceinline__ void mma16816(float* c, const uint32_t* a, const uint32_t* b) {
    asm("mma.sync.aligned.m16n8k16.row.col.f32.bf16.bf16.f32 "
        "{%0,%1,%2,%3}, {%4,%5,%6,%7}, {%8,%9}, {%0,%1,%2,%3};\n"
        : "+f"(c[0]), "+f"(c[1]), "+f"(c[2]), "+f"(c[3])
        : "r"(a[0]), "r"(a[1]), "r"(a[2]), "r"(a[3]), "r"(b[0]), "r"(b[1]));
}
static __device__ __forceinline__ void mma3(float* c, const uint32_t* ah, const uint32_t* al,
                                            const uint32_t* bh, const uint32_t* bl) {
    mma16816(c, ah, bh); mma16816(c, al, bh); mma16816(c, ah, bl);
}
static __device__ __forceinline__ void split2(float a, float b, uint32_t& hi, uint32_t& lo) {
    __nv_bfloat16 ha = __float2bfloat16(a), hb = __float2bfloat16(b);
    __nv_bfloat16 la = __float2bfloat16(a - __bfloat162float(ha));
    __nv_bfloat16 lb = __float2bfloat16(b - __bfloat162float(hb));
    __nv_bfloat162 Hh; Hh.x = ha; Hh.y = hb; hi = *(uint32_t*)&Hh;
    __nv_bfloat162 Ll; Ll.x = la; Ll.y = lb; lo = *(uint32_t*)&Ll;
}
static __device__ __forceinline__ void split8(const float4& x0, const float4& x1,
                                              uint4& H, uint4& L) {
    split2(x0.x, x0.y, H.x, L.x);
    split2(x0.z, x0.w, H.y, L.y);
    split2(x1.x, x1.y, H.z, L.z);
    split2(x1.z, x1.w, H.w, L.w);
}

// 64x64 warp tile over a staged chunk (dense GEMMs). acc[4 mf][8 nf][4].
template<int PITCH, int KSTEPS>
static __device__ __forceinline__ void compute64(
    const __nv_bfloat16* Ah, const __nv_bfloat16* Al,
    const __nv_bfloat16* Bh, const __nv_bfloat16* Bl,
    float (&acc)[4][8][4], int wm, int wn, int lane)
{
    const int arow = wm * 64 + (lane & 15);
    const int brow = wn * 64 + (lane & 7) + ((lane & 16) ? 8 : 0);
#pragma unroll
    for (int s = 0; s < KSTEPS; s++) {
        const int ak = s * 16 + ((lane & 16) ? 8 : 0);
        const int bk = s * 16 + ((lane & 8) ? 8 : 0);
        uint32_t ah[4][4], al[4][4];
#pragma unroll
        for (int mf = 0; mf < 4; mf++) {
            ldsm4(ah[mf], s2u(&Ah[(arow + 16 * mf) * PITCH + ak]));
            ldsm4(al[mf], s2u(&Al[(arow + 16 * mf) * PITCH + ak]));
        }
#pragma unroll
        for (int j = 0; j < 4; j++) {
            uint32_t th[4], tl[4];
            ldsm4(th, s2u(&Bh[(brow + 16 * j) * PITCH + bk]));
            ldsm4(tl, s2u(&Bl[(brow + 16 * j) * PITCH + bk]));
#pragma unroll
            for (int mf = 0; mf < 4; mf++) {
                mma16816(acc[mf][2*j],   ah[mf], th);
                mma16816(acc[mf][2*j+1], ah[mf], th + 2);
                mma16816(acc[mf][2*j],   al[mf], th);
                mma16816(acc[mf][2*j+1], al[mf], th + 2);
                mma16816(acc[mf][2*j],   ah[mf], tl);
                mma16816(acc[mf][2*j+1], ah[mf], tl + 2);
            }
        }
    }
}

// ---------------------------------------------------------------------------
// Kernel 0: pre-split q,k,v and the 4 weights into bf16 hi/lo. grid(4096,7).
// ---------------------------------------------------------------------------
__global__ __launch_bounds__(256) void k_presplit(
    const float* __restrict__ q, const float* __restrict__ k, const float* __restrict__ v,
    const float* __restrict__ wq, const float* __restrict__ wk,
    const float* __restrict__ wv, const float* __restrict__ wo)
{
    const int z = blockIdx.y;
    const float* src;
    __nv_bfloat16 *dh, *dl;
    size_t n;
    if (z < 3) {
        src = (z == 0) ? q : (z == 1) ? k : v;
        dh = g_Xh + (size_t)z * M_ * E_;
        dl = g_Xl + (size_t)z * M_ * E_;
        n = (size_t)M_ * E_;
    } else {
        int w = z - 3;
        src = (w == 0) ? wq : (w == 1) ? wk : (w == 2) ? wv : wo;
        dh = g_Wh + (size_t)w * E_ * E_;
        dl = g_Wl + (size_t)w * E_ * E_;
        n = (size_t)E_ * E_;
    }
    size_t base = ((size_t)blockIdx.x * 256 + threadIdx.x) * 8;
    if (base >= n) return;
    float4 x0 = *(const float4*)&src[base];
    float4 x1 = *(const float4*)&src[base + 4];
    uint4 H, L;
    split8(x0, x1, H, L);
    *(uint4*)&dh[base] = H;
    *(uint4*)&dl[base] = L;
}

// ---------------------------------------------------------------------------
// Kernel 1: QKV projections. block 256x128, 256 thr, cp.async pipelined.
// ---------------------------------------------------------------------------
__global__ __launch_bounds__(256) void k_qkv(
    const float* __restrict__ bq, const float* __restrict__ bk, const float* __restrict__ bv)
{
    extern __shared__ char dsm[];
    const int z = blockIdx.z;
    const __nv_bfloat16* Xh = g_Xh + (size_t)z * M_ * E_;
    const __nv_bfloat16* Xl = g_Xl + (size_t)z * M_ * E_;
    const __nv_bfloat16* Wh = g_Wh + (size_t)z * E_ * E_;
    const __nv_bfloat16* Wl = g_Wl + (size_t)z * E_ * E_;
    const float* bias = (z == 0) ? bq : (z == 1) ? bk : bv;
    __nv_bfloat16* dsth = (z == 0) ? g_Qh : (z == 1) ? g_Kh : g_Vh;
    __nv_bfloat16* dstl = (z == 0) ? g_Ql : (z == 1) ? g_Kl : g_Vl;

    const int tid = threadIdx.x, wid = tid >> 5, lane = tid & 31;
    const int wm = wid >> 1, wn = wid & 1;
    const int row0 = blockIdx.x * 256, col0 = blockIdx.y * 128;

    auto stage = [&](int buf, int kt) {
        uint32_t sb = s2u(dsm) + buf * QBUF;
#pragma unroll
        for (int i = 0; i < 4; i++) {
            int ch = tid + i * 256;
            int r = ch >> 2, c = ch & 3;
            uint32_t d = sb + r * (PA * 2) + c * 16;
            size_t so = (size_t)(row0 + r) * E_ + kt + c * 8;
            cpa16(d, Xh + so);
            cpa16(d + TQA, Xl + so);
        }
#pragma unroll
        for (int i = 0; i < 2; i++) {
            int ch = tid + i * 256;
            int r = ch >> 2, c = ch & 3;
            uint32_t d = sb + 2 * TQA + r * (PA * 2) + c * 16;
            size_t so = (size_t)(col0 + r) * E_ + kt + c * 8;
            cpa16(d, Wh + so);
            cpa16(d + TQB, Wl + so);
        }
    };

    float acc[4][8][4];
#pragma unroll
    for (int a = 0; a < 4; a++)
#pragma unroll
        for (int bn = 0; bn < 8; bn++)
#pragma unroll
            for (int e = 0; e < 4; e++) acc[a][bn][e] = 0.f;

    stage(0, 0); cpa_commit();
    cpa_wait<0>(); __syncthreads();

    const int NCH = E_ / 32;
    for (int c = 0; c < NCH; c++) {
        if (c + 1 < NCH) { stage((c + 1) & 1, (c + 1) * 32); cpa_commit(); }
        char* bb = dsm + (c & 1) * QBUF;
        compute64<PA, 2>((__nv_bfloat16*)bb, (__nv_bfloat16*)(bb + TQA),
                         (__nv_bfloat16*)(bb + 2 * TQA), (__nv_bfloat16*)(bb + 2 * TQA + TQB),
                         acc, wm, wn, lane);
        if (c + 1 < NCH) { cpa_wait<0>(); __syncthreads(); }
    }
    __syncthreads();

    // epilogue via smem fp32
    float* st = (float*)dsm;
    const int g = lane >> 2, c2 = (lane & 3) * 2;
#pragma unroll
    for (int mf = 0; mf < 4; mf++)
#pragma unroll
        for (int nf = 0; nf < 8; nf++) {
            int row = wm * 64 + mf * 16 + g, col = wn * 64 + nf * 8 + c2;
            *(float2*)&st[row * EPIT + col] = make_float2(acc[mf][nf][0], acc[mf][nf][1]);
            *(float2*)&st[(row + 8) * EPIT + col] = make_float2(acc[mf][nf][2], acc[mf][nf][3]);
        }
    __syncthreads();
#pragma unroll
    for (int i = 0; i < 16; i++) {
        int idx = tid + i * 256;          // 4096 groups of 8 cols
        int g8 = idx & 15, m = idx >> 4;
        int cbase = g8 * 8;
        float4 x0 = *(float4*)&st[m * EPIT + cbase];
        float4 x1 = *(float4*)&st[m * EPIT + cbase + 4];
        int n0 = col0 + cbase;
        x0.x += __ldg(&bias[n0]);     x0.y += __ldg(&bias[n0 + 1]);
        x0.z += __ldg(&bias[n0 + 2]); x0.w += __ldg(&bias[n0 + 3]);
        x1.x += __ldg(&bias[n0 + 4]); x1.y += __ldg(&bias[n0 + 5]);
        x1.z += __ldg(&bias[n0 + 6]); x1.w += __ldg(&bias[n0 + 7]);
        uint4 Hv, Lv;
        split8(x0, x1, Hv, Lv);
        int mm = row0 + m;
        int b = mm >> 11, s = mm & (S_ - 1);
        int hd = n0 >> 6, d = n0 & 63;
        size_t o = (((size_t)(b * H_ + hd)) * S_ + s) * DH_ + d;
        *(uint4*)&dsth[o] = Hv;
        *(uint4*)&dstl[o] = Lv;
    }
}

// ---------------------------------------------------------------------------
// Kernel 2: softmax stats via recomputed QK^T. Warp tile = 16 rows x 128 cols,
// Q frags in registers, K double-buffered. grid(16, 64), 256 thr, 2 CTAs/SM.
// ---------------------------------------------------------------------------
__global__ void __launch_bounds__(256, 2) k_sstats()
{
    extern __shared__ char dsm[];
    const int qt = 15 - blockIdx.x, bhd = blockIdx.y;
    const int row0 = qt * 128;
    const int tid = threadIdx.x, w = tid >> 5, lane = tid & 31;
    const int g = lane >> 2, qd = lane & 3;
    const __nv_bfloat16* Qh = g_Qh + (size_t)bhd * S_ * DH_;
    const __nv_bfloat16* Ql = g_Ql + (size_t)bhd * S_ * DH_;
    const __nv_bfloat16* Kh = g_Kh + (size_t)bhd * S_ * DH_;
    const __nv_bfloat16* Kl = g_Kl + (size_t)bhd * S_ * DH_;
    const uint32_t sb = s2u(dsm);

    // stage Q 128x64 hi/lo
#pragma unroll
    for (int i = 0; i < 4; i++) {
        int ch = tid + i * 256, r = ch >> 3, c = ch & 7;
        cpa16(sb + r * PSB + c * 16, Qh + (size_t)(row0 + r) * DH_ + c * 8);
        cpa16(sb + THL + r * PSB + c * 16, Ql + (size_t)(row0 + r) * DH_ + c * 8);
    }
    cpa_commit(); cpa_wait<0>(); __syncthreads();

    uint32_t qfh[4][4], qfl[4][4];
#pragma unroll
    for (int ks = 0; ks < 4; ks++) {
        uint32_t a = sb + (w * 16 + (lane & 15)) * PSB + (ks * 16 + ((lane & 16) ? 8 : 0)) * 2;
        ldsm4(qfh[ks], a);
        ldsm4(qfl[ks], a + THL);
    }

    const int r0 = row0 + w * 16 + g, r1 = r0 + 8;
    float mi0 = -1e30f, mi1 = -1e30f, li0 = 0.f, li1 = 0.f;

    auto stageK = [&](int buf, int t) {
        uint32_t kb = sb + TPAIR + buf * TPAIR;
#pragma unroll
        for (int i = 0; i < 4; i++) {
            int ch = tid + i * 256, r = ch >> 3, c = ch & 7;
            cpa16(kb + r * PSB + c * 16, Kh + (size_t)(t * 128 + r) * DH_ + c * 8);
            cpa16(kb + THL + r * PSB + c * 16, Kl + (size_t)(t * 128 + r) * DH_ + c * 8);
        }
    };

    const int NT = qt + 1;
    stageK(0, 0); cpa_commit();
    for (int t = 0; t < NT; t++) {
        if (t + 1 < NT) { stageK((t + 1) & 1, t + 1); cpa_commit(); cpa_wait<1>(); }
        else            { cpa_wait<0>(); }
        __syncthreads();
        const uint32_t kb = sb + TPAIR + (t & 1) * TPAIR;
        const bool diag = (t == qt);
        const int colb = t * 128;
#pragma unroll
        for (int j = 0; j < 8; j++) {
            float ct0[4] = {0.f, 0.f, 0.f, 0.f};
            float ct1[4] = {0.f, 0.f, 0.f, 0.f};
#pragma unroll
            for (int ks = 0; ks < 4; ks++) {
                uint32_t addr = kb + (j * 16 + (lane & 7) + ((lane & 16) ? 8 : 0)) * PSB
                              + (ks * 16 + ((lane & 8) ? 8 : 0)) * 2;
                uint32_t bh4[4], bl4[4];
                ldsm4(bh4, addr); ldsm4(bl4, addr + THL);
                mma3(ct0, qfh[ks], qfl[ks], bh4, bl4);
                mma3(ct1, qfh[ks], qfl[ks], bh4 + 2, bl4 + 2);
            }
            const int c0 = colb + j * 16 + 2 * qd, c1 = c0 + 8;
            float v0 = ct0[0] * 0.125f, v1 = ct0[1] * 0.125f;
            float v2 = ct1[0] * 0.125f, v3 = ct1[1] * 0.125f;
            float u0 = ct0[2] * 0.125f, u1 = ct0[3] * 0.125f;
            float u2 = ct1[2] * 0.125f, u3 = ct1[3] * 0.125f;
            if (diag) {
                if (c0     > r0) v0 = -1e30f;
                if (c0 + 1 > r0) v1 = -1e30f;
                if (c1     > r0) v2 = -1e30f;
                if (c1 + 1 > r0) v3 = -1e30f;
                if (c0     > r1) u0 = -1e30f;
                if (c0 + 1 > r1) u1 = -1e30f;
                if (c1     > r1) u2 = -1e30f;
                if (c1 + 1 > r1) u3 = -1e30f;
            }
            float mt = fmaxf(fmaxf(v0, v1), fmaxf(v2, v3));
            if (mt > mi0) { li0 *= __expf(mi0 - mt); mi0 = mt; }
            if (mi0 > -9e29f)
                li0 += __expf(v0 - mi0) + __expf(v1 - mi0) + __expf(v2 - mi0) + __expf(v3 - mi0);
            mt = fmaxf(fmaxf(u0, u1), fmaxf(u2, u3));
            if (mt > mi1) { li1 *= __expf(mi1 - mt); mi1 = mt; }
            if (mi1 > -9e29f)
                li1 += __expf(u0 - mi1) + __expf(u1 - mi1) + __expf(u2 - mi1) + __expf(u3 - mi1);
        }
        __syncthreads();
    }

    // quad reduction (lanes qd=0..3 share each row)
    float mm0 = fmaxf(mi0, __shfl_xor_sync(0xffffffffu, mi0, 1));
    mm0 = fmaxf(mm0, __shfl_xor_sync(0xffffffffu, mm0, 2));
    float ls0 = (mi0 > -9e29f) ? li0 * __expf(mi0 - mm0) : 0.f;
    ls0 += __shfl_xor_sync(0xffffffffu, ls0, 1);
    ls0 += __shfl_xor_sync(0xffffffffu, ls0, 2);
    float mm1 = fmaxf(mi1, __shfl_xor_sync(0xffffffffu, mi1, 1));
    mm1 = fmaxf(mm1, __shfl_xor_sync(0xffffffffu, mm1, 2));
    float ls1 = (mi1 > -9e29f) ? li1 * __expf(mi1 - mm1) : 0.f;
    ls1 += __shfl_xor_sync(0xffffffffu, ls1, 1);
    ls1 += __shfl_xor_sync(0xffffffffu, ls1, 2);
    if (qd == 0) {
        g_m[(size_t)bhd * S_ + r0] = mm0;
        g_linv[(size_t)bhd * S_ + r0] = 1.f / ls0;
        g_m[(size_t)bhd * S_ + r1] = mm1;
        g_linv[(size_t)bhd * S_ + r1] = 1.f / ls1;
    }
}

// ---------------------------------------------------------------------------
// Kernel 3: fused attention pass 2: S recompute -> probs (write to attn) ->
// PV mma with P fragments reused as A-operands. grid(16, 64), 256 thr.
// ---------------------------------------------------------------------------
__global__ void __launch_bounds__(256) k_attn(float* __restrict__ attn)
{
    extern __shared__ char dsm[];
    const int qt = 15 - blockIdx.x, bhd = blockIdx.y;
    const int row0 = qt * 128;
    const int tid = threadIdx.x, w = tid >> 5, lane = tid & 31;
    const int g = lane >> 2, qd = lane & 3;
    float* P = attn + (size_t)bhd * S_ * S_;
    const __nv_bfloat16* Qh = g_Qh + (size_t)bhd * S_ * DH_;
    const __nv_bfloat16* Ql = g_Ql + (size_t)bhd * S_ * DH_;
    const __nv_bfloat16* Kh = g_Kh + (size_t)bhd * S_ * DH_;
    const __nv_bfloat16* Kl = g_Kl + (size_t)bhd * S_ * DH_;
    const __nv_bfloat16* Vh = g_Vh + (size_t)bhd * S_ * DH_;
    const __nv_bfloat16* Vl = g_Vl + (size_t)bhd * S_ * DH_;
    const int bb = bhd >> 4, hd = bhd & 15;
    const uint32_t sb = s2u(dsm);

    // stage Q 128x64 hi/lo
#pragma unroll
    for (int i = 0; i < 4; i++) {
        int ch = tid + i * 256, r = ch >> 3, c = ch & 7;
        cpa16(sb + r * PSB + c * 16, Qh + (size_t)(row0 + r) * DH_ + c * 8);
        cpa16(sb + THL + r * PSB + c * 16, Ql + (size_t)(row0 + r) * DH_ + c * 8);
    }
    cpa_commit(); cpa_wait<0>(); __syncthreads();

    uint32_t qfh[4][4], qfl[4][4];
#pragma unroll
    for (int ks = 0; ks < 4; ks++) {
        uint32_t a = sb + (w * 16 + (lane & 15)) * PSB + (ks * 16 + ((lane & 16) ? 8 : 0)) * 2;
        ldsm4(qfh[ks], a);
        ldsm4(qfl[ks], a + THL);
    }

    const int r0 = row0 + w * 16 + g, r1 = r0 + 8;
    const float m0 = g_m[(size_t)bhd * S_ + r0], li0 = g_linv[(size_t)bhd * S_ + r0];
    const float m1 = g_m[(size_t)bhd * S_ + r1], li1 = g_linv[(size_t)bhd * S_ + r1];

    auto stageKV = [&](int buf, int t) {
        uint32_t kb = sb + TPAIR + buf * TPAIR;
        uint32_t vb = sb + 3 * TPAIR + buf * TPAIR;
#pragma unroll
        for (int i = 0; i < 4; i++) {
            int ch = tid + i * 256, r = ch >> 3, c = ch & 7;
            size_t so = (size_t)(t * 128 + r) * DH_ + c * 8;
            cpa16(kb + r * PSB + c * 16, Kh + so);
            cpa16(kb + THL + r * PSB + c * 16, Kl + so);
            cpa16(vb + r * PSB + c * 16, Vh + so);
            cpa16(vb + THL + r * PSB + c * 16, Vl + so);
        }
    };

    float accO[8][4];
#pragma unroll
    for (int nf = 0; nf < 8; nf++)
#pragma unroll
        for (int e = 0; e < 4; e++) accO[nf][e] = 0.f;

    const int NT = qt + 1;
    stageKV(0, 0); cpa_commit();
    for (int t = 0; t < NT; t++) {
        if (t + 1 < NT) { stageKV((t + 1) & 1, t + 1); cpa_commit(); cpa_wait<1>(); }
        else            { cpa_wait<0>(); }
        __syncthreads();
        const uint32_t kb = sb + TPAIR + (t & 1) * TPAIR;
        const uint32_t vb = sb + 3 * TPAIR + (t & 1) * TPAIR;
        const int colb = t * 128;

        // ---- S = Q K^T (16 n8-tiles per warp) ----
        float sc[16][4];
#pragma unroll
        for (int nf = 0; nf < 16; nf++)
#pragma unroll
            for (int e = 0; e < 4; e++) sc[nf][e] = 0.f;
#pragma unroll
        for (int ks = 0; ks < 4; ks++) {
#pragma unroll
            for (int j = 0; j < 8; j++) {
                uint32_t addr = kb + (j * 16 + (lane & 7) + ((lane & 16) ? 8 : 0)) * PSB
                              + (ks * 16 + ((lane & 8) ? 8 : 0)) * 2;
                uint32_t bh4[4], bl4[4];
                ldsm4(bh4, addr); ldsm4(bl4, addr + THL);
                mma3(sc[2*j],     qfh[ks], qfl[ks], bh4, bl4);
                mma3(sc[2*j + 1], qfh[ks], qfl[ks], bh4 + 2, bl4 + 2);
            }
        }

        // ---- probs: p = exp(s/8 - m) * linv, write final attn, keep in sc ----
#pragma unroll
        for (int nf = 0; nf < 16; nf++) {
            const int c0 = colb + nf * 8 + 2 * qd;
            float p0 = (c0     <= r0) ? __expf(sc[nf][0] * 0.125f - m0) * li0 : 0.f;
            float p1 = (c0 + 1 <= r0) ? __expf(sc[nf][1] * 0.125f - m0) * li0 : 0.f;
            float p2 = (c0     <= r1) ? __expf(sc[nf][2] * 0.125f - m1) * li1 : 0.f;
            float p3 = (c0 + 1 <= r1) ? __expf(sc[nf][3] * 0.125f - m1) * li1 : 0.f;
            *(float2*)&P[(size_t)r0 * S_ + c0] = make_float2(p0, p1);
            *(float2*)&P[(size_t)r1 * S_ + c0] = make_float2(p2, p3);
            sc[nf][0] = p0; sc[nf][1] = p1; sc[nf][2] = p2; sc[nf][3] = p3;
        }

        // ---- PV: P fragments -> A-operands (C->A identity), V via ldsm4t ----
#pragma unroll
        for (int ks2 = 0; ks2 < 8; ks2++) {
            uint32_t pah[4], pal[4];
            split2(sc[2*ks2][0],     sc[2*ks2][1],     pah[0], pal[0]);
            split2(sc[2*ks2][2],     sc[2*ks2][3],     pah[1], pal[1]);
            split2(sc[2*ks2 + 1][0], sc[2*ks2 + 1][1], pah[2], pal[2]);
            split2(sc[2*ks2 + 1][2], sc[2*ks2 + 1][3], pah[3], pal[3]);
#pragma unroll
            for (int dg = 0; dg < 4; dg++) {
                uint32_t addr = vb + (ks2 * 16 + (lane & 7) + ((lane & 8) ? 8 : 0)) * PSB
                              + (dg * 16 + ((lane & 16) ? 8 : 0)) * 2;
                uint32_t vh4[4], vl4[4];
                ldsm4t(vh4, addr); ldsm4t(vl4, addr + THL);
                mma3(accO[2*dg],     pah, pal, vh4, vl4);
                mma3(accO[2*dg + 1], pah, pal, vh4 + 2, vl4 + 2);
            }
        }
        __syncthreads();
    }

    // ---- zero-fill the strict-upper tiles of this row band ----
    for (int t2 = NT; t2 < 16; t2++) {
        float4 z = make_float4(0.f, 0.f, 0.f, 0.f);
#pragma unroll
        for (int i = 0; i < 16; i++) {
            int idx = tid + i * 256;
            int r = idx >> 5, c = (idx & 31) * 4;
            *(float4*)&P[(size_t)(row0 + r) * S_ + t2 * 128 + c] = z;
        }
    }

    // ---- O epilogue: split bf16 context into g_Ch/g_Cl ----
#pragma unroll
    for (int nf = 0; nf < 8; nf++) {
        const int col = hd * DH_ + nf * 8 + 2 * qd;
        size_t o0 = ((size_t)(bb * S_ + r0)) * E_ + col;
        size_t o1 = ((size_t)(bb * S_ + r1)) * E_ + col;
        uint32_t h, l;
        split2(accO[nf][0], accO[nf][1], h, l);
        *(uint32_t*)&g_Ch[o0] = h; *(uint32_t*)&g_Cl[o0] = l;
        split2(accO[nf][2], accO[nf][3], h, l);
        *(uint32_t*)&g_Ch[o1] = h; *(uint32_t*)&g_Cl[o1] = l;
    }
}

// ---------------------------------------------------------------------------
// Kernel 4: out = Ctx @ wo^T + bo. grid(32,8), 256 thr.
// ---------------------------------------------------------------------------
__global__ __launch_bounds__(256) void k_oproj(
    const float* __restrict__ bo, float* __restrict__ out)
{
    extern __shared__ char dsm[];
    const __nv_bfloat16* Wh = g_Wh + (size_t)3 * E_ * E_;
    const __nv_bfloat16* Wl = g_Wl + (size_t)3 * E_ * E_;

    const int tid = threadIdx.x, wid = tid >> 5, lane = tid & 31;
    const int wm = wid >> 1, wn = wid & 1;
    const int row0 = blockIdx.x * 256, col0 = blockIdx.y * 128;

    auto stage = [&](int buf, int kt) {
        uint32_t sb = s2u(dsm) + buf * QBUF;
#pragma unroll
        for (int i = 0; i < 4; i++) {
            int ch = tid + i * 256;
            int r = ch >> 2, c = ch & 3;
            uint32_t d = sb + r * (PA * 2) + c * 16;
            size_t so = (size_t)(row0 + r) * E_ + kt + c * 8;
            cpa16(d, g_Ch + so);
            cpa16(d + TQA, g_Cl + so);
        }
#pragma unroll
        for (int i = 0; i < 2; i++) {
            int ch = tid + i * 256;
            int r = ch >> 2, c = ch & 3;
            uint32_t d = sb + 2 * TQA + r * (PA * 2) + c * 16;
            size_t so = (size_t)(col0 + r) * E_ + kt + c * 8;
            cpa16(d, Wh + so);
            cpa16(d + TQB, Wl + so);
        }
    };

    float acc[4][8][4];
#pragma unroll
    for (int a = 0; a < 4; a++)
#pragma unroll
        for (int bn = 0; bn < 8; bn++)
#pragma unroll
            for (int e = 0; e < 4; e++) acc[a][bn][e] = 0.f;

    stage(0, 0); cpa_commit();
    cpa_wait<0>(); __syncthreads();

    const int NCH = E_ / 32;
    for (int c = 0; c < NCH; c++) {
        if (c + 1 < NCH) { stage((c + 1) & 1, (c + 1) * 32); cpa_commit(); }
        char* bb = dsm + (c & 1) * QBUF;
        compute64<PA, 2>((__nv_bfloat16*)bb, (__nv_bfloat16*)(bb + TQA),
                         (__nv_bfloat16*)(bb + 2 * TQA), (__nv_bfloat16*)(bb + 2 * TQA + TQB),
                         acc, wm, wn, lane);
        if (c + 1 < NCH) { cpa_wait<0>(); __syncthreads(); }
    }
    __syncthreads();

    float* st = (float*)dsm;
    const int g = lane >> 2, c2 = (lane & 3) * 2;
#pragma unroll
    for (int mf = 0; mf < 4; mf++)
#pragma unroll
        for (int nf = 0; nf < 8; nf++) {
            int row = wm * 64 + mf * 16 + g, col = wn * 64 + nf * 8 + c2;
            *(float2*)&st[row * EPIT + col] = make_float2(acc[mf][nf][0], acc[mf][nf][1]);
            *(float2*)&st[(row + 8) * EPIT + col] = make_float2(acc[mf][nf][2], acc[mf][nf][3]);
        }
    __syncthreads();
#pragma unroll
    for (int i = 0; i < 32; i++) {
        int idx = tid + i * 256;                 // 8192 float4 groups
        int c4 = idx & 31, m = idx >> 5;
        float4 x = *(float4*)&st[m * EPIT + c4 * 4];
        int n0 = col0 + c4 * 4;
        x.x += __ldg(&bo[n0]);     x.y += __ldg(&bo[n0 + 1]);
        x.z += __ldg(&bo[n0 + 2]); x.w += __ldg(&bo[n0 + 3]);
        *(float4*)&out[(size_t)(row0 + m) * E_ + n0] = x;
    }
}

// ---------------------------------------------------------------------------
extern "C" void kernel_launch(void* const* d_in, const int* in_sizes, int n_in,
                              void* d_out, int out_size)
{
    const float* q  = (const float*)d_in[0];
    const float* k  = (const float*)d_in[1];
    const float* v  = (const float*)d_in[2];
    const float* wq = (const float*)d_in[3];
    const float* bq = (const float*)d_in[4];
    const float* wk = (const float*)d_in[5];
    const float* bk = (const float*)d_in[6];
    const float* wv = (const float*)d_in[7];
    const float* bv = (const float*)d_in[8];
    const float* wo = (const float*)d_in[9];
    const float* bo = (const float*)d_in[10];

    float* out  = (float*)d_out;                       // [B,S,E]
    float* attn = out + (size_t)B_ * S_ * E_;          // [B,H,S,S]

    cudaFuncSetAttribute(k_qkv,    cudaFuncAttributeMaxDynamicSharedMemorySize, DSM_Q);
    cudaFuncSetAttribute(k_sstats, cudaFuncAttributeMaxDynamicSharedMemorySize, DSM_ST);
    cudaFuncSetAttribute(k_attn,   cudaFuncAttributeMaxDynamicSharedMemorySize, DSM_AT);
    cudaFuncSetAttribute(k_oproj,  cudaFuncAttributeMaxDynamicSharedMemorySize, DSM_Q);

    k_presplit<<<dim3(4096, 7), 256>>>(q, k, v, wq, wk, wv, wo);
    k_qkv    <<<dim3(M_/256, E_/128, 3), 256, DSM_Q>>>(bq, bk, bv);
    k_sstats <<<dim3(16, BH_), 256, DSM_ST>>>();
    k_attn   <<<dim3(16, BH_), 256, DSM_AT>>>(attn);
    k_oproj  <<<dim3(M_/256, E_/128), 256, DSM_Q>>>(bo, out);
}